// round 14
// baseline (speedup 1.0000x reference)
#include <cuda_runtime.h>
#include <cuda_fp16.h>
#include <cstdint>

#define NE 100000
#define NR 100
#define D  128
#define NB 10
#define NL 2
#define EG 600000
#define EPB 2048
#define EG_GRID 296     // persistent blocks, occ 2 on 148 SMs
#define NSELF 782       // ceil(NE/128)
#define NT 128          // threads per CTA (4 warps, 2x2 grid of m64 x n64 tiles)

// ---------------- scratch (device globals: no allocation allowed) ----------------
__device__ __align__(256) unsigned g_AGGh[(size_t)NE*64];   // edge msg sum, packed half2 (atomics)
__device__ __align__(256) unsigned g_SELFh[(size_t)NE*64];  // self-term + bias, packed half2
__device__ float g_indeg[NE];
__device__ int   g_cnt[NR];
__device__ int   g_off[NR+1];
__device__ int   g_cur[NR];
__device__ int   g_ord[EG];                // edge ids grouped by relation
__device__ int   g_tiles[8192];            // flat tile table: (r<<16)|t ; r==NR -> self tile
__device__ int   g_ntile_all;
// fp16 operands (single precision-level)
__device__ uint4 g_Wh4[(size_t)NL*NR*2048];   // 32KB per (l,r): Wt[n][k] fp16, swizzled rows
__device__ uint4 g_SWh4[(size_t)NL*2048];     // self_w transposed fp16
__device__ uint4 g_Xh4[(size_t)NE*16];        // row-major: 128 fp16 per row (256B)

// SMEM layout (dynamic, bytes): idx, 1 A buf, B  -> 67584 B (occ 2)
#define SM_TGT 0
#define SM_WGT 512
#define SM_A   2048
#define SM_BH  (SM_A + 32768)
#define SM_TOT (SM_BH + 32768)

// ---------------- helpers ----------------
__device__ __forceinline__ void red16h(unsigned* p, unsigned a, unsigned b, unsigned c, unsigned d){
    asm volatile("red.global.add.noftz.v4.f16x2 [%0], {%1,%2,%3,%4};"
                 :: "l"(p), "r"(a), "r"(b), "r"(c), "r"(d) : "memory");
}
__device__ __forceinline__ void cpa16(uint32_t dst, const void* src){
    asm volatile("cp.async.cg.shared.global [%0], [%1], 16;" :: "r"(dst), "l"(src) : "memory");
}
#define CP_COMMIT() asm volatile("cp.async.commit_group;" ::: "memory")
#define CP_WAIT0()  asm volatile("cp.async.wait_group 0;" ::: "memory")

__device__ __forceinline__ unsigned packh2(float a, float b){
    __half2 h = __floats2half2_rn(a, b);
    return *reinterpret_cast<unsigned*>(&h);
}
__device__ __forceinline__ uint4 pack8h(const float* v){
    return make_uint4(packh2(v[0],v[1]), packh2(v[2],v[3]),
                      packh2(v[4],v[5]), packh2(v[6],v[7]));
}
__device__ __forceinline__ float2 h2f(unsigned u){
    return __half22float2(*reinterpret_cast<__half2*>(&u));
}
__device__ __forceinline__ uint32_t smem_u32(const void* p){
    uint32_t a;
    asm("{ .reg .u64 t; cvta.to.shared.u64 t, %1; cvt.u32.u64 %0, t; }" : "=r"(a) : "l"(p));
    return a;
}
// row-major tile, 256B rows, 16B chunks XOR-swizzled by row
__device__ __forceinline__ uint32_t swa(uint32_t base, int r, int c){
    return base + r*256 + (((c ^ (r & 7)) & 15) << 4);
}
#define LDSM4(d0,d1,d2,d3,a) asm volatile( \
    "ldmatrix.sync.aligned.m8n8.x4.shared.b16 {%0,%1,%2,%3}, [%4];" \
    : "=r"(d0),"=r"(d1),"=r"(d2),"=r"(d3) : "r"(a))
#define MMA16816(c,a0,a1,a2,a3,b0,b1) asm volatile( \
    "mma.sync.aligned.m16n8k16.row.col.f32.f16.f16.f32 " \
    "{%0,%1,%2,%3},{%4,%5,%6,%7},{%8,%9},{%0,%1,%2,%3};" \
    : "+f"((c)[0]),"+f"((c)[1]),"+f"((c)[2]),"+f"((c)[3]) \
    : "r"(a0),"r"(a1),"r"(a2),"r"(a3),"r"(b0),"r"(b1))

// 128x128x128 mainloop, 2x2 warp grid: warp tile m64 x n64
__device__ __forceinline__ void mma_loop(uint32_t aT, uint32_t bH,
                                         int lane, int mw, int nw, float acc[4][8][4]){
    int ar = mw*64 + (lane & 15);
    int ac_sel = lane >> 4;
    int br = nw*64 + ((lane >> 4) & 1)*8 + (lane & 7);
    int bc_sel = (lane >> 3) & 1;
    for (int ks = 0; ks < 8; ks++){
        int ac = ks*2 + ac_sel;
        int bc = ks*2 + bc_sel;
        uint32_t a[4][4], bh[8][2];
#pragma unroll
        for (int mi = 0; mi < 4; mi++)
            LDSM4(a[mi][0],a[mi][1],a[mi][2],a[mi][3], swa(aT, ar+mi*16, ac));
#pragma unroll
        for (int p = 0; p < 4; p++)
            LDSM4(bh[2*p][0],bh[2*p][1],bh[2*p+1][0],bh[2*p+1][1], swa(bH, br+p*16, bc));
#pragma unroll
        for (int mi = 0; mi < 4; mi++)
#pragma unroll
        for (int nf = 0; nf < 8; nf++)
            MMA16816(acc[mi][nf], a[mi][0],a[mi][1],a[mi][2],a[mi][3], bh[nf][0],bh[nf][1]);
    }
}

// ---------------- prep kernels ----------------
// fused: zero indeg/cnt/AGGh + convert x0 -> fp16
__global__ void k_init(const float* __restrict__ x){
    int i = blockIdx.x*blockDim.x + threadIdx.x;
    if (i < NE) g_indeg[i] = 0.f;
    if (i < NR) g_cnt[i] = 0;
    if (i < NE*16){
        ((uint4*)g_AGGh)[i] = make_uint4(0,0,0,0);
        const float4* s = (const float4*)x + (size_t)i*2;
        float4 a = s[0], b = s[1];
        float v[8] = {a.x,a.y,a.z,a.w,b.x,b.y,b.z,b.w};
        g_Xh4[i] = pack8h(v);
    }
}

__global__ void k_hist(const int* __restrict__ tgt, const int* __restrict__ et){
    __shared__ int lcnt[NR];
    int tid = threadIdx.x;
    for (int i = tid; i < NR; i += 256) lcnt[i] = 0;
    __syncthreads();
    int e0 = blockIdx.x*EPB;
#pragma unroll
    for (int q = 0; q < EPB/256; q++){
        int e = e0 + q*256 + tid;
        if (e < EG){
            atomicAdd(&g_indeg[tgt[e]], 1.f);
            atomicAdd(&lcnt[et[e]], 1);
        }
    }
    __syncthreads();
    for (int i = tid; i < NR; i += 256)
        if (lcnt[i]) atomicAdd(&g_cnt[i], lcnt[i]);
}

// offsets + flat tile table (edge tiles, then NSELF self tiles with r==NR)
__global__ void k_scan(){
    __shared__ int ptil[NR];
    __shared__ int strun;
    int tid = threadIdx.x;
    if (tid == 0){
        int run = 0, trun = 0;
        for (int r = 0; r < NR; r++){
            g_off[r] = run; g_cur[r] = run;
            ptil[r] = trun;
            trun += (g_cnt[r] + 127) >> 7;
            run += g_cnt[r];
        }
        g_off[NR] = run;
        strun = trun;
        g_ntile_all = trun + NSELF;
    }
    __syncthreads();
    for (int r = tid; r < NR; r += blockDim.x){
        int nt = (g_cnt[r] + 127) >> 7;
        int base = ptil[r];
        for (int t = 0; t < nt; t++) g_tiles[base + t] = (r << 16) | t;
    }
    int et = strun;
    for (int t = tid; t < NSELF; t += blockDim.x)
        g_tiles[et + t] = (NR << 16) | t;
}

__global__ void k_scatter(const int* __restrict__ et){
    __shared__ int lcnt[NR];
    __shared__ int lbase[NR];
    int tid = threadIdx.x;
    for (int i = tid; i < NR; i += 256) lcnt[i] = 0;
    __syncthreads();
    int e0 = blockIdx.x*EPB;
    int rel[EPB/256], lpos[EPB/256];
#pragma unroll
    for (int q = 0; q < EPB/256; q++){
        int e = e0 + q*256 + tid;
        if (e < EG){
            rel[q]  = et[e];
            lpos[q] = atomicAdd(&lcnt[rel[q]], 1);
        }
    }
    __syncthreads();
    for (int i = tid; i < NR; i += 256)
        if (lcnt[i]) lbase[i] = atomicAdd(&g_cur[i], lcnt[i]);
    __syncthreads();
#pragma unroll
    for (int q = 0; q < EPB/256; q++){
        int e = e0 + q*256 + tid;
        if (e < EG) g_ord[lbase[rel[q]] + lpos[q]] = e;
    }
}

// fused W build: blocks [0, NL*NR): Wt; blocks [NL*NR, NL*NR+NL): self_w transposed
__global__ void k_relw_hf(const float* __restrict__ bases, const float* __restrict__ coefs,
                          const float* __restrict__ selfw){
    int blk = blockIdx.x;
    if (blk < NL*NR){
        int lr = blk;
        float c[NB];
#pragma unroll
        for (int b = 0; b < NB; b++) c[b] = coefs[lr*NB + b];
        char* wh = (char*)g_Wh4 + (size_t)lr*32768;
        for (int ch = threadIdx.x; ch < 2048; ch += blockDim.x){
            int n  = ch & 127;
            int kc = ch >> 7;
            float v[8];
#pragma unroll
            for (int j = 0; j < 8; j++){
                int k = kc*8 + j;
                float a = 0.f;
#pragma unroll
                for (int b = 0; b < NB; b++) a += c[b]*bases[b*D*D + k*D + n];
                v[j] = a;
            }
            int off = n*256 + (((kc ^ (n & 7)) & 15) << 4);
            *(uint4*)(wh + off) = pack8h(v);
        }
    } else {
        int l = blk - NL*NR;
        char* wh = (char*)g_SWh4 + (size_t)l*32768;
        for (int ch = threadIdx.x; ch < 2048; ch += blockDim.x){
            int n  = ch & 127;
            int kc = ch >> 7;
            float v[8];
#pragma unroll
            for (int j = 0; j < 8; j++)
                v[j] = selfw[(size_t)l*D*D + (kc*8 + j)*D + n];
            int off = n*256 + (((kc ^ (n & 7)) & 15) << 4);
            *(uint4*)(wh + off) = pack8h(v);
        }
    }
}

// ---------------- fused GEMM: edge tiles (v4 atomic->AGGh) + self tiles (store->SELFh) ----------------
__global__ void __launch_bounds__(NT,2) k_gemm(const int* __restrict__ src,
        const int* __restrict__ tgt, const float* __restrict__ bias, int layer){
    int ntile = g_ntile_all;
    int per = (ntile + gridDim.x - 1) / gridDim.x;
    int i0 = blockIdx.x*per;
    int i1 = min(i0 + per, ntile);
    if (i0 >= i1) return;   // uniform before any barrier

    extern __shared__ __align__(16) char smem[];
    uint32_t sb = smem_u32(smem);
    int tid = threadIdx.x, lane = tid & 31, wid = tid >> 5;
    int mw = wid >> 1, nw = wid & 1;

    float2 bs[8];
#pragma unroll
    for (int nf = 0; nf < 8; nf++)
        bs[nf] = *(const float2*)(bias + layer*D + nw*64 + nf*8 + (lane & 3)*2);

    auto idx_load = [&](int ent, int& srow, int& tg, float& fl){
        int r = ent >> 16, t = ent & 0xffff;
        if (r == NR){
            srow = min(t*128 + tid, NE-1); tg = 0; fl = 0.f;
        } else {
            int s0 = g_off[r];
            int valid = min(128, g_off[r+1] - s0 - t*128);
            int e = g_ord[s0 + t*128 + min(tid, valid-1)];
            srow = src[e];
            tg = tgt[e];
            fl = (tid < valid) ? 1.f : 0.f;
        }
    };
    auto copyB = [&](int r){
        const uint4* wh = (r == NR) ? (g_SWh4 + (size_t)layer*2048)
                                    : (g_Wh4 + ((size_t)layer*NR + r)*2048);
        for (int i = tid; i < 2048; i += NT)
            cpa16(sb + SM_BH + (uint32_t)(i*16), wh + i);
    };
    auto gatherA = [&](int srow, int tg, float fl){
        const uint4* xh = g_Xh4 + (size_t)srow*16;
        uint32_t rbase = sb + SM_A + (uint32_t)(tid*256);
        int rsw = tid & 7;
#pragma unroll
        for (int j = 0; j < 16; j++)
            cpa16(rbase + (uint32_t)((((j ^ rsw) & 15)) << 4), xh + j);
        ((int*)(smem + SM_TGT))[tid] = tg;
        ((float*)(smem + SM_WGT))[tid] = fl;
    };

    // prologue
    int ent_cur = g_tiles[i0];
    int cur_r = ent_cur >> 16;
    int srow, tg; float fl;
    idx_load(ent_cur, srow, tg, fl);
    copyB(cur_r);
    gatherA(srow, tg, fl);
    CP_COMMIT();

    int ent_next = 0;
    for (int i = i0; i < i1; i++){
        bool more = (i + 1 < i1);
        if (more){ ent_next = g_tiles[i + 1]; idx_load(ent_next, srow, tg, fl); }
        CP_WAIT0();
        __syncthreads();

        bool isSelf = (ent_cur >> 16) == NR;
        int tgr[4][2]; float wgr[4][2];
        if (!isSelf){
            int* s_tgt = (int*)(smem + SM_TGT);
            float* s_wgt = (float*)(smem + SM_WGT);
            int rb = mw*64 + (lane >> 2);
#pragma unroll
            for (int mi = 0; mi < 4; mi++)
#pragma unroll
                for (int h = 0; h < 2; h++){
                    int rr = rb + mi*16 + h*8;
                    tgr[mi][h] = s_tgt[rr];
                    wgr[mi][h] = s_wgt[rr];
                }
        }

        float acc[4][8][4];
#pragma unroll
        for (int mi = 0; mi < 4; mi++)
#pragma unroll
            for (int nf = 0; nf < 8; nf++)
#pragma unroll
                for (int q = 0; q < 4; q++) acc[mi][nf][q] = 0.f;

        mma_loop(sb + SM_A, sb + SM_BH, lane, mw, nw, acc);
        __syncthreads();                         // A/B/idx reads done

        if (more){                               // overlap next gather with epilogue
            int rn = ent_next >> 16;
            if (rn != cur_r){ copyB(rn); cur_r = rn; }
            gatherA(srow, tg, fl);
            CP_COMMIT();
        }

        if (isSelf){
            int t = ent_cur & 0xffff;
#pragma unroll
            for (int mi = 0; mi < 4; mi++){
                int r0 = t*128 + mw*64 + mi*16 + (lane >> 2);
#pragma unroll
                for (int nf = 0; nf < 8; nf++){
                    int cu = nw*32 + nf*4 + (lane & 3);
                    if (r0 < NE)
                        g_SELFh[(size_t)r0*64 + cu] = packh2(acc[mi][nf][0] + bs[nf].x,
                                                             acc[mi][nf][1] + bs[nf].y);
                    if (r0 + 8 < NE)
                        g_SELFh[(size_t)(r0+8)*64 + cu] = packh2(acc[mi][nf][2] + bs[nf].x,
                                                                 acc[mi][nf][3] + bs[nf].y);
                }
            }
        } else {
            // edge epilogue: assemble 16B per row (unscaled msg), one v4.f16x2 atomic per 8 cols
            int odd = lane & 1;
#pragma unroll
            for (int mi = 0; mi < 4; mi++){
                float flv = wgr[mi][odd];
                int   tt = tgr[mi][odd];
                unsigned* rowp = g_AGGh + (size_t)tt*64 + nw*32;
#pragma unroll
                for (int nf = 0; nf < 8; nf++){
                    float c0 = acc[mi][nf][0], c1 = acc[mi][nf][1];
                    float c2 = acc[mi][nf][2], c3 = acc[mi][nf][3];
                    float s0 = __shfl_xor_sync(0xffffffffu, odd ? c0 : c2, 1);
                    float s1 = __shfl_xor_sync(0xffffffffu, odd ? c1 : c3, 1);
                    float v0, v1, v2, v3;
                    if (!odd){ v0 = c0; v1 = c1; v2 = s0; v3 = s1; }
                    else     { v0 = s0; v1 = s1; v2 = c2; v3 = c3; }
                    unsigned p0 = packh2(v0, v1);
                    unsigned p1 = packh2(v2, v3);
                    unsigned q0 = __shfl_xor_sync(0xffffffffu, p0, 2);
                    unsigned q1 = __shfl_xor_sync(0xffffffffu, p1, 2);
                    if (!(lane & 2) && flv != 0.f)
                        red16h(rowp + nf*4, p0, p1, q0, q1);
                }
            }
        }
        ent_cur = ent_next;
    }
}

// ---------------- ReLU: relu(SELFh + winv*AGGh); repack (L0, +zero AGGh) or fp32 out (L1) ----
__global__ void k_relu(float* __restrict__ dout, int layer){
    int i = blockIdx.x*blockDim.x + threadIdx.x;
    if (i < NE*16){
        int row = i >> 4;
        float winv = 1.f / fmaxf(g_indeg[row], 1.f);
        uint4 a = ((const uint4*)g_AGGh)[i];
        uint4 s = ((const uint4*)g_SELFh)[i];
        float2 f0 = h2f(a.x), f1 = h2f(a.y), f2 = h2f(a.z), f3 = h2f(a.w);
        float2 g0 = h2f(s.x), g1 = h2f(s.y), g2 = h2f(s.z), g3 = h2f(s.w);
        f0.x = fmaxf(fmaf(f0.x, winv, g0.x), 0.f); f0.y = fmaxf(fmaf(f0.y, winv, g0.y), 0.f);
        f1.x = fmaxf(fmaf(f1.x, winv, g1.x), 0.f); f1.y = fmaxf(fmaf(f1.y, winv, g1.y), 0.f);
        f2.x = fmaxf(fmaf(f2.x, winv, g2.x), 0.f); f2.y = fmaxf(fmaf(f2.y, winv, g2.y), 0.f);
        f3.x = fmaxf(fmaf(f3.x, winv, g3.x), 0.f); f3.y = fmaxf(fmaf(f3.y, winv, g3.y), 0.f);
        if (layer == 0){
            g_Xh4[i] = make_uint4(packh2(f0.x,f0.y), packh2(f1.x,f1.y),
                                  packh2(f2.x,f2.y), packh2(f3.x,f3.y));
            ((uint4*)g_AGGh)[i] = make_uint4(0,0,0,0);   // ready for layer 1 atomics
        } else {
            float4* o = (float4*)dout + (size_t)i*2;
            o[0] = make_float4(f0.x, f0.y, f1.x, f1.y);
            o[1] = make_float4(f2.x, f2.y, f3.x, f3.y);
        }
    }
}

// ---------------- launch ----------------
extern "C" void kernel_launch(void* const* d_in, const int* in_sizes, int n_in,
                              void* d_out, int out_size){
    const float* x0    = (const float*)d_in[0];
    const float* bases = (const float*)d_in[1];
    const float* coefs = (const float*)d_in[2];
    const float* selfw = (const float*)d_in[3];
    const float* bias  = (const float*)d_in[4];
    const int*   source= (const int*)d_in[5];
    const int*   target= (const int*)d_in[6];
    const int*   etype = (const int*)d_in[7];
    float* out = (float*)d_out;

    static int inited = 0;
    if (!inited){
        cudaFuncSetAttribute(k_gemm, cudaFuncAttributeMaxDynamicSharedMemorySize, SM_TOT);
        inited = 1;
    }

    k_init<<<(NE*16+255)/256, 256>>>(x0);
    k_hist<<<(EG+EPB-1)/EPB, 256>>>(target, etype);
    k_scan<<<1, 128>>>();
    k_scatter<<<(EG+EPB-1)/EPB, 256>>>(etype);
    k_relw_hf<<<NL*NR + NL, 256>>>(bases, coefs, selfw);

    for (int l = 0; l < NL; l++){
        k_gemm<<<EG_GRID, NT, SM_TOT>>>(source, target, bias, l);
        k_relu<<<(NE*16+255)/256, 256>>>(out, l);
    }
}

// round 15
// speedup vs baseline: 1.0339x; 1.0339x over previous
#include <cuda_runtime.h>
#include <cuda_fp16.h>
#include <cstdint>

#define NE 100000
#define NR 100
#define D  128
#define NB 10
#define NL 2
#define EG 600000
#define EPB 2048
#define EG_GRID 296     // persistent blocks, occ 2 on 148 SMs
#define NSELF 782       // ceil(NE/128)

// ---------------- scratch (device globals: no allocation allowed) ----------------
__device__ __align__(256) unsigned g_AGGh[(size_t)NE*64];   // edge msg sum, packed half2 (atomics)
__device__ __align__(256) unsigned g_SELFh[(size_t)NE*64];  // self-term + bias, packed half2
__device__ float g_indeg[NE];
__device__ int   g_cnt[NR];
__device__ int   g_off[NR+1];
__device__ int   g_cur[NR];
__device__ int   g_ord[EG];                // edge ids grouped by relation
__device__ int   g_tiles[8192];            // flat tile table: (r<<16)|t ; r==NR -> self tile
__device__ int   g_ntile_all;
// fp16 operands (single precision-level)
__device__ uint4 g_Wh4[(size_t)NL*NR*2048];   // 32KB per (l,r): Wt[n][k] fp16, swizzled rows
__device__ uint4 g_SWh4[(size_t)NL*2048];     // self_w transposed fp16
__device__ uint4 g_Xh4[(size_t)NE*16];        // row-major: 128 fp16 per row (256B)

// SMEM layout (dynamic, bytes): 2 idx bufs, 2 A bufs, B  -> 100352 B (occ 2: 200.7KB/SM)
#define SM_IDX(b) ((b)*1024)               // tgt 512B + wgt 512B per buffer
#define SM_A(b)   (2048 + (b)*32768)
#define SM_BH     (2048 + 65536)
#define SM_TOT    (SM_BH + 32768)

// ---------------- helpers ----------------
__device__ __forceinline__ void red16h(unsigned* p, unsigned a, unsigned b, unsigned c, unsigned d){
    asm volatile("red.global.add.noftz.v4.f16x2 [%0], {%1,%2,%3,%4};"
                 :: "l"(p), "r"(a), "r"(b), "r"(c), "r"(d) : "memory");
}
__device__ __forceinline__ void cpa16(uint32_t dst, const void* src){
    asm volatile("cp.async.cg.shared.global [%0], [%1], 16;" :: "r"(dst), "l"(src) : "memory");
}
#define CP_COMMIT() asm volatile("cp.async.commit_group;" ::: "memory")
#define CP_WAIT0()  asm volatile("cp.async.wait_group 0;" ::: "memory")

__device__ __forceinline__ unsigned packh2(float a, float b){
    __half2 h = __floats2half2_rn(a, b);
    return *reinterpret_cast<unsigned*>(&h);
}
__device__ __forceinline__ uint4 pack8h(const float* v){
    return make_uint4(packh2(v[0],v[1]), packh2(v[2],v[3]),
                      packh2(v[4],v[5]), packh2(v[6],v[7]));
}
__device__ __forceinline__ float2 h2f(unsigned u){
    return __half22float2(*reinterpret_cast<__half2*>(&u));
}
__device__ __forceinline__ uint32_t smem_u32(const void* p){
    uint32_t a;
    asm("{ .reg .u64 t; cvta.to.shared.u64 t, %1; cvt.u32.u64 %0, t; }" : "=r"(a) : "l"(p));
    return a;
}
// row-major tile, 256B rows, 16B chunks XOR-swizzled by row
__device__ __forceinline__ uint32_t swa(uint32_t base, int r, int c){
    return base + r*256 + (((c ^ (r & 7)) & 15) << 4);
}
#define LDSM4(d0,d1,d2,d3,a) asm volatile( \
    "ldmatrix.sync.aligned.m8n8.x4.shared.b16 {%0,%1,%2,%3}, [%4];" \
    : "=r"(d0),"=r"(d1),"=r"(d2),"=r"(d3) : "r"(a))
#define MMA16816(c,a0,a1,a2,a3,b0,b1) asm volatile( \
    "mma.sync.aligned.m16n8k16.row.col.f32.f16.f16.f32 " \
    "{%0,%1,%2,%3},{%4,%5,%6,%7},{%8,%9},{%0,%1,%2,%3};" \
    : "+f"((c)[0]),"+f"((c)[1]),"+f"((c)[2]),"+f"((c)[3]) \
    : "r"(a0),"r"(a1),"r"(a2),"r"(a3),"r"(b0),"r"(b1))

// 128x128x128 mainloop, 4x2 warp grid: warp tile m32 x n64
__device__ __forceinline__ void mma_loop(uint32_t aT, uint32_t bH,
                                         int lane, int mw, int nw, float acc[2][8][4]){
    int ar = mw*32 + (lane & 15);
    int ac_sel = lane >> 4;
    int br = nw*64 + ((lane >> 4) & 1)*8 + (lane & 7);
    int bc_sel = (lane >> 3) & 1;
    for (int ks = 0; ks < 8; ks++){
        int ac = ks*2 + ac_sel;
        int bc = ks*2 + bc_sel;
        uint32_t a[2][4], bh[8][2];
#pragma unroll
        for (int mi = 0; mi < 2; mi++)
            LDSM4(a[mi][0],a[mi][1],a[mi][2],a[mi][3], swa(aT, ar+mi*16, ac));
#pragma unroll
        for (int p = 0; p < 4; p++)
            LDSM4(bh[2*p][0],bh[2*p][1],bh[2*p+1][0],bh[2*p+1][1], swa(bH, br+p*16, bc));
#pragma unroll
        for (int mi = 0; mi < 2; mi++)
#pragma unroll
        for (int nf = 0; nf < 8; nf++)
            MMA16816(acc[mi][nf], a[mi][0],a[mi][1],a[mi][2],a[mi][3], bh[nf][0],bh[nf][1]);
    }
}

// ---------------- prep kernels ----------------
// fused: zero indeg/cnt/AGGh + convert x0 -> fp16
__global__ void k_init(const float* __restrict__ x){
    int i = blockIdx.x*blockDim.x + threadIdx.x;
    if (i < NE) g_indeg[i] = 0.f;
    if (i < NR) g_cnt[i] = 0;
    if (i < NE*16){
        ((uint4*)g_AGGh)[i] = make_uint4(0,0,0,0);
        const float4* s = (const float4*)x + (size_t)i*2;
        float4 a = s[0], b = s[1];
        float v[8] = {a.x,a.y,a.z,a.w,b.x,b.y,b.z,b.w};
        g_Xh4[i] = pack8h(v);
    }
}

__global__ void k_hist(const int* __restrict__ tgt, const int* __restrict__ et){
    __shared__ int lcnt[NR];
    int tid = threadIdx.x;
    for (int i = tid; i < NR; i += 256) lcnt[i] = 0;
    __syncthreads();
    int e0 = blockIdx.x*EPB;
#pragma unroll
    for (int q = 0; q < EPB/256; q++){
        int e = e0 + q*256 + tid;
        if (e < EG){
            atomicAdd(&g_indeg[tgt[e]], 1.f);
            atomicAdd(&lcnt[et[e]], 1);
        }
    }
    __syncthreads();
    for (int i = tid; i < NR; i += 256)
        if (lcnt[i]) atomicAdd(&g_cnt[i], lcnt[i]);
}

// offsets + flat tile table (edge tiles, then NSELF self tiles with r==NR)
__global__ void k_scan(){
    __shared__ int ptil[NR];
    __shared__ int strun;
    int tid = threadIdx.x;
    if (tid == 0){
        int run = 0, trun = 0;
        for (int r = 0; r < NR; r++){
            g_off[r] = run; g_cur[r] = run;
            ptil[r] = trun;
            trun += (g_cnt[r] + 127) >> 7;
            run += g_cnt[r];
        }
        g_off[NR] = run;
        strun = trun;
        g_ntile_all = trun + NSELF;
    }
    __syncthreads();
    for (int r = tid; r < NR; r += blockDim.x){
        int nt = (g_cnt[r] + 127) >> 7;
        int base = ptil[r];
        for (int t = 0; t < nt; t++) g_tiles[base + t] = (r << 16) | t;
    }
    int et = strun;
    for (int t = tid; t < NSELF; t += blockDim.x)
        g_tiles[et + t] = (NR << 16) | t;
}

__global__ void k_scatter(const int* __restrict__ et){
    __shared__ int lcnt[NR];
    __shared__ int lbase[NR];
    int tid = threadIdx.x;
    for (int i = tid; i < NR; i += 256) lcnt[i] = 0;
    __syncthreads();
    int e0 = blockIdx.x*EPB;
    int rel[EPB/256], lpos[EPB/256];
#pragma unroll
    for (int q = 0; q < EPB/256; q++){
        int e = e0 + q*256 + tid;
        if (e < EG){
            rel[q]  = et[e];
            lpos[q] = atomicAdd(&lcnt[rel[q]], 1);
        }
    }
    __syncthreads();
    for (int i = tid; i < NR; i += 256)
        if (lcnt[i]) lbase[i] = atomicAdd(&g_cur[i], lcnt[i]);
    __syncthreads();
#pragma unroll
    for (int q = 0; q < EPB/256; q++){
        int e = e0 + q*256 + tid;
        if (e < EG) g_ord[lbase[rel[q]] + lpos[q]] = e;
    }
}

// fused W build: blocks [0, NL*NR): Wt; blocks [NL*NR, NL*NR+NL): self_w transposed
__global__ void k_relw_hf(const float* __restrict__ bases, const float* __restrict__ coefs,
                          const float* __restrict__ selfw){
    int blk = blockIdx.x;
    if (blk < NL*NR){
        int lr = blk;
        float c[NB];
#pragma unroll
        for (int b = 0; b < NB; b++) c[b] = coefs[lr*NB + b];
        char* wh = (char*)g_Wh4 + (size_t)lr*32768;
        for (int ch = threadIdx.x; ch < 2048; ch += blockDim.x){
            int n  = ch & 127;
            int kc = ch >> 7;
            float v[8];
#pragma unroll
            for (int j = 0; j < 8; j++){
                int k = kc*8 + j;
                float a = 0.f;
#pragma unroll
                for (int b = 0; b < NB; b++) a += c[b]*bases[b*D*D + k*D + n];
                v[j] = a;
            }
            int off = n*256 + (((kc ^ (n & 7)) & 15) << 4);
            *(uint4*)(wh + off) = pack8h(v);
        }
    } else {
        int l = blk - NL*NR;
        char* wh = (char*)g_SWh4 + (size_t)l*32768;
        for (int ch = threadIdx.x; ch < 2048; ch += blockDim.x){
            int n  = ch & 127;
            int kc = ch >> 7;
            float v[8];
#pragma unroll
            for (int j = 0; j < 8; j++)
                v[j] = selfw[(size_t)l*D*D + (kc*8 + j)*D + n];
            int off = n*256 + (((kc ^ (n & 7)) & 15) << 4);
            *(uint4*)(wh + off) = pack8h(v);
        }
    }
}

// ---------------- fused GEMM: edge tiles (v4 atomic->AGGh) + self tiles (store->SELFh) ----------------
__global__ void __launch_bounds__(256,2) k_gemm(const int* __restrict__ src,
        const int* __restrict__ tgt, const float* __restrict__ bias, int layer){
    int ntile = g_ntile_all;
    int per = (ntile + gridDim.x - 1) / gridDim.x;
    int i0 = blockIdx.x*per;
    int i1 = min(i0 + per, ntile);
    if (i0 >= i1) return;   // uniform before any barrier

    extern __shared__ __align__(16) char smem[];
    uint32_t sb = smem_u32(smem);
    int tid = threadIdx.x, lane = tid & 31, wid = tid >> 5;
    int mw = wid & 3, nw = wid >> 2;
    int gr = tid >> 1, gh = tid & 1;

    float2 bs[8];
#pragma unroll
    for (int nf = 0; nf < 8; nf++)
        bs[nf] = *(const float2*)(bias + layer*D + nw*64 + nf*8 + (lane & 3)*2);

    auto idx_load = [&](int ent, int& srow, int& tg, float& fl){
        int r = ent >> 16, t = ent & 0xffff;
        if (r == NR){
            srow = min(t*128 + gr, NE-1); tg = 0; fl = 0.f;
        } else {
            int s0 = g_off[r];
            int valid = min(128, g_off[r+1] - s0 - t*128);
            int e = g_ord[s0 + t*128 + min(gr, valid-1)];
            srow = src[e];
            tg = tgt[e];
            fl = (gr < valid) ? 1.f : 0.f;
        }
    };
    auto copyB = [&](int r){
        const uint4* wh = (r == NR) ? (g_SWh4 + (size_t)layer*2048)
                                    : (g_Wh4 + ((size_t)layer*NR + r)*2048);
        for (int i = tid; i < 2048; i += 256)
            cpa16(sb + SM_BH + (uint32_t)(i*16), wh + i);
    };
    auto gatherA = [&](int srow, int tg, float fl, int b){
        const uint4* xh = g_Xh4 + (size_t)srow*16 + gh*8;
        uint32_t ab = sb + SM_A(b);
#pragma unroll
        for (int j = 0; j < 8; j++){
            int c = gh*8 + j;
            uint32_t off = (uint32_t)(gr*256 + (((c ^ (gr & 7)) & 15) << 4));
            cpa16(ab + off, xh + j);
        }
        if (gh == 0){
            ((int*)(smem + SM_IDX(b)))[gr] = tg;
            ((float*)(smem + SM_IDX(b) + 512))[gr] = fl;
        }
    };

    // prologue: B + A(i0) into buf 0
    int ent_cur = g_tiles[i0];
    int cur_r = ent_cur >> 16;
    int srow, tg; float fl;
    idx_load(ent_cur, srow, tg, fl);
    copyB(cur_r);
    gatherA(srow, tg, fl, 0);
    CP_COMMIT();

    int buf = 0;
    int ent_next = 0;
    for (int i = i0; i < i1; i++){
        bool more = (i + 1 < i1);
        if (more){ ent_next = g_tiles[i + 1]; idx_load(ent_next, srow, tg, fl); }
        CP_WAIT0();
        __syncthreads();                 // A[buf] + idx[buf] + B ready

        // issue next A gather into the other buffer NOW (covered by mma + epilogue)
        if (more){
            gatherA(srow, tg, fl, buf^1);
            CP_COMMIT();
        }

        bool isSelf = (ent_cur >> 16) == NR;
        int tgr[2][2]; float wgr[2][2];
        if (!isSelf){
            int* s_tgt = (int*)(smem + SM_IDX(buf));
            float* s_wgt = (float*)(smem + SM_IDX(buf) + 512);
            int rb = mw*32 + (lane >> 2);
#pragma unroll
            for (int mi = 0; mi < 2; mi++)
#pragma unroll
                for (int h = 0; h < 2; h++){
                    int rr = rb + mi*16 + h*8;
                    tgr[mi][h] = s_tgt[rr];
                    wgr[mi][h] = s_wgt[rr];
                }
        }

        float acc[2][8][4];
#pragma unroll
        for (int mi = 0; mi < 2; mi++)
#pragma unroll
            for (int nf = 0; nf < 8; nf++)
#pragma unroll
                for (int q = 0; q < 4; q++) acc[mi][nf][q] = 0.f;

        mma_loop(sb + SM_A(buf), sb + SM_BH, lane, mw, nw, acc);
        __syncthreads();                 // B reads done (safe to overwrite B)

        if (more){
            int rn = ent_next >> 16;
            if (rn != cur_r){ copyB(rn); cur_r = rn; CP_COMMIT(); }
        }

        if (isSelf){
            int t = ent_cur & 0xffff;
#pragma unroll
            for (int mi = 0; mi < 2; mi++){
                int r0 = t*128 + mw*32 + mi*16 + (lane >> 2);
#pragma unroll
                for (int nf = 0; nf < 8; nf++){
                    int cu = nw*32 + nf*4 + (lane & 3);
                    if (r0 < NE)
                        g_SELFh[(size_t)r0*64 + cu] = packh2(acc[mi][nf][0] + bs[nf].x,
                                                             acc[mi][nf][1] + bs[nf].y);
                    if (r0 + 8 < NE)
                        g_SELFh[(size_t)(r0+8)*64 + cu] = packh2(acc[mi][nf][2] + bs[nf].x,
                                                                 acc[mi][nf][3] + bs[nf].y);
                }
            }
        } else {
            // edge epilogue: assemble 16B per row (unscaled msg), one v4.f16x2 atomic per 8 cols
            int odd = lane & 1;
#pragma unroll
            for (int mi = 0; mi < 2; mi++){
                float flv = wgr[mi][odd];
                int   tt = tgr[mi][odd];
                unsigned* rowp = g_AGGh + (size_t)tt*64 + nw*32;
#pragma unroll
                for (int nf = 0; nf < 8; nf++){
                    float c0 = acc[mi][nf][0], c1 = acc[mi][nf][1];
                    float c2 = acc[mi][nf][2], c3 = acc[mi][nf][3];
                    float s0 = __shfl_xor_sync(0xffffffffu, odd ? c0 : c2, 1);
                    float s1 = __shfl_xor_sync(0xffffffffu, odd ? c1 : c3, 1);
                    float v0, v1, v2, v3;
                    if (!odd){ v0 = c0; v1 = c1; v2 = s0; v3 = s1; }
                    else     { v0 = s0; v1 = s1; v2 = c2; v3 = c3; }
                    unsigned p0 = packh2(v0, v1);
                    unsigned p1 = packh2(v2, v3);
                    unsigned q0 = __shfl_xor_sync(0xffffffffu, p0, 2);
                    unsigned q1 = __shfl_xor_sync(0xffffffffu, p1, 2);
                    if (!(lane & 2) && flv != 0.f)
                        red16h(rowp + nf*4, p0, p1, q0, q1);
                }
            }
        }
        ent_cur = ent_next;
        buf ^= 1;
    }
}

// ---------------- ReLU: relu(SELFh + winv*AGGh); repack (L0, +zero AGGh) or fp32 out (L1) ----
__global__ void k_relu(float* __restrict__ dout, int layer){
    int i = blockIdx.x*blockDim.x + threadIdx.x;
    if (i < NE*16){
        int row = i >> 4;
        float winv = 1.f / fmaxf(g_indeg[row], 1.f);
        uint4 a = ((const uint4*)g_AGGh)[i];
        uint4 s = ((const uint4*)g_SELFh)[i];
        float2 f0 = h2f(a.x), f1 = h2f(a.y), f2 = h2f(a.z), f3 = h2f(a.w);
        float2 g0 = h2f(s.x), g1 = h2f(s.y), g2 = h2f(s.z), g3 = h2f(s.w);
        f0.x = fmaxf(fmaf(f0.x, winv, g0.x), 0.f); f0.y = fmaxf(fmaf(f0.y, winv, g0.y), 0.f);
        f1.x = fmaxf(fmaf(f1.x, winv, g1.x), 0.f); f1.y = fmaxf(fmaf(f1.y, winv, g1.y), 0.f);
        f2.x = fmaxf(fmaf(f2.x, winv, g2.x), 0.f); f2.y = fmaxf(fmaf(f2.y, winv, g2.y), 0.f);
        f3.x = fmaxf(fmaf(f3.x, winv, g3.x), 0.f); f3.y = fmaxf(fmaf(f3.y, winv, g3.y), 0.f);
        if (layer == 0){
            g_Xh4[i] = make_uint4(packh2(f0.x,f0.y), packh2(f1.x,f1.y),
                                  packh2(f2.x,f2.y), packh2(f3.x,f3.y));
            ((uint4*)g_AGGh)[i] = make_uint4(0,0,0,0);   // ready for layer 1 atomics
        } else {
            float4* o = (float4*)dout + (size_t)i*2;
            o[0] = make_float4(f0.x, f0.y, f1.x, f1.y);
            o[1] = make_float4(f2.x, f2.y, f3.x, f3.y);
        }
    }
}

// ---------------- launch ----------------
extern "C" void kernel_launch(void* const* d_in, const int* in_sizes, int n_in,
                              void* d_out, int out_size){
    const float* x0    = (const float*)d_in[0];
    const float* bases = (const float*)d_in[1];
    const float* coefs = (const float*)d_in[2];
    const float* selfw = (const float*)d_in[3];
    const float* bias  = (const float*)d_in[4];
    const int*   source= (const int*)d_in[5];
    const int*   target= (const int*)d_in[6];
    const int*   etype = (const int*)d_in[7];
    float* out = (float*)d_out;

    static int inited = 0;
    if (!inited){
        cudaFuncSetAttribute(k_gemm, cudaFuncAttributeMaxDynamicSharedMemorySize, SM_TOT);
        inited = 1;
    }

    k_init<<<(NE*16+255)/256, 256>>>(x0);
    k_hist<<<(EG+EPB-1)/EPB, 256>>>(target, etype);
    k_scan<<<1, 128>>>();
    k_scatter<<<(EG+EPB-1)/EPB, 256>>>(etype);
    k_relw_hf<<<NL*NR + NL, 256>>>(bases, coefs, selfw);

    for (int l = 0; l < NL; l++){
        k_gemm<<<EG_GRID, 256, SM_TOT>>>(source, target, bias, l);
        k_relu<<<(NE*16+255)/256, 256>>>(out, l);
    }
}